// round 9
// baseline (speedup 1.0000x reference)
#include <cuda_runtime.h>
#include <math.h>
#include <stdint.h>

#define N    2048
#define DIN  256
#define DK   64
#define DV   64
#define DR   64
#define PCOLS 256

#define RPB  4          // output rows per block
#define TPB  256
#define CJ   32         // j per chunk
#define NCHUNK (N / CJ) // 64

// separate projection buffers (contiguous 64-float rows each)
__device__ float g_Q[N * DK];
__device__ float g_K[N * DK];
__device__ float g_V[N * DV];
__device__ float g_R[N * DR];

// dynamic smem layout (floats):
//   bufD : 2 * RPB * CJ * DR   = 16384   (64 KB)  D chunk double buffer
//   w    : RPB * N             =  8192   (32 KB)  scores -> probs
//   red  : TPB                 =   256
//   misc : 8
#define SMEM_FLOATS (2 * RPB * CJ * DR + RPB * N + TPB + 8)
#define SMEM_BYTES  (SMEM_FLOATS * 4)

__device__ __forceinline__ float dot4(float4 a, float4 b) {
    return a.x * b.x + a.y * b.y + a.z * b.z + a.w * b.w;
}

__device__ __forceinline__ void cp_async16(void* s, const void* g) {
    uint32_t sa = (uint32_t)__cvta_generic_to_shared(s);
    asm volatile("cp.async.cg.shared.global [%0], [%1], 16;\n" :: "r"(sa), "l"(g));
}
__device__ __forceinline__ void cp_commit() {
    asm volatile("cp.async.commit_group;\n");
}
template <int n>
__device__ __forceinline__ void cp_wait() {
    asm volatile("cp.async.wait_group %0;\n" :: "n"(n));
}

// 16-lane-group reduction of 4 accumulators: 5 shfls.
// On return lanes with sub<4 hold the total of acc[sub].
__device__ __forceinline__ float reduce4x16(const float* acc, int sub) {
    float v01 = (sub & 1) ? acc[1] : acc[0];
    float o01 = (sub & 1) ? acc[0] : acc[1];
    v01 += __shfl_xor_sync(0xFFFFFFFFu, o01, 1);
    float v23 = (sub & 1) ? acc[3] : acc[2];
    float o23 = (sub & 1) ? acc[2] : acc[3];
    v23 += __shfl_xor_sync(0xFFFFFFFFu, o23, 1);
    float v = (sub & 2) ? v23 : v01;
    float o = (sub & 2) ? v01 : v23;
    v += __shfl_xor_sync(0xFFFFFFFFu, o, 2);
    v += __shfl_xor_sync(0xFFFFFFFFu, v, 4);
    v += __shfl_xor_sync(0xFFFFFFFFu, v, 8);
    return v;
}

// ---------------------------------------------------------------------------
// Kernel 1: proj = H @ W^T, scattered into g_Q / g_K / g_V / g_R
// ---------------------------------------------------------------------------
__global__ void proj_kernel(const float* __restrict__ H,
                            const float* __restrict__ W) {
    __shared__ float Hs[16][17];
    __shared__ float Ws[16][17];
    const int row = blockIdx.y * 16 + threadIdx.y;
    const int colBase = blockIdx.x * 16;

    float acc = 0.f;
    for (int k0 = 0; k0 < DIN; k0 += 16) {
        Hs[threadIdx.y][threadIdx.x] = H[row * DIN + k0 + threadIdx.x];
        Ws[threadIdx.y][threadIdx.x] = W[(colBase + threadIdx.y) * DIN + k0 + threadIdx.x];
        __syncthreads();
#pragma unroll
        for (int kk = 0; kk < 16; kk++)
            acc += Hs[threadIdx.y][kk] * Ws[threadIdx.x][kk];
        __syncthreads();
    }
    const int col = colBase + threadIdx.x;
    const int within = col & 63;
    float* dst = (col < 64) ? g_Q : (col < 128) ? g_K : (col < 192) ? g_V : g_R;
    dst[row * 64 + within] = acc;
}

// ---------------------------------------------------------------------------
// Kernel 2: fused attention with cp.async double-buffered D stream.
// ---------------------------------------------------------------------------
__global__ void __launch_bounds__(TPB, 2)
attn_kernel(const float* __restrict__ D, float* __restrict__ out) {
    extern __shared__ float smem[];
    float4* bufD4 = (float4*)smem;                          // [2][RPB*CJ*16] float4
    float*  w     = smem + 2 * RPB * CJ * DR;               // [RPB][N]
    float*  red   = w + RPB * N;                            // [TPB]
    float*  inv_sum = red + TPB;                            // [RPB]

    const int tid  = threadIdx.x;
    const int lane = tid & 31;
    const int sub  = lane & 15;
    const int gid  = tid >> 4;       // 16-lane group id, 0..15
    const int i0   = blockIdx.x * RPB;
    const float scale = rsqrtf((float)(DK + DR));

    const float4* D4  = (const float4*)D;     // [(i*N+j)*16 + k]
    const float4* gQ4 = (const float4*)g_Q;
    const float4* gK4 = (const float4*)g_K;
    const float4* gR4 = (const float4*)g_R;

    // per-lane slices of Q and R for RPB rows, pre-scaled so w holds
    // scale*(QK + RD) directly and softmax needs no extra multiply.
    float4 q_reg[RPB], r_reg[RPB];
#pragma unroll
    for (int r = 0; r < RPB; r++) {
        float4 q = gQ4[(size_t)(i0 + r) * 16 + sub];
        float4 rr = gR4[(size_t)(i0 + r) * 16 + sub];
        q.x *= scale; q.y *= scale; q.z *= scale; q.w *= scale;
        rr.x *= scale; rr.y *= scale; rr.z *= scale; rr.w *= scale;
        q_reg[r] = q; r_reg[r] = rr;
    }

    // ---- issue cp.async prologue for chunks 0,1 (overlaps with phase 0) ----
    // each thread copies 8 x 16B per chunk: unit in [0, 2048)
    //   r = unit>>9, (j_local*16 + k4) = unit&511
#pragma unroll
    for (int c = 0; c < 2; c++) {
#pragma unroll
        for (int u = 0; u < 8; u++) {
            const int unit = tid + u * TPB;
            const int r = unit >> 9, rem = unit & 511;
            cp_async16(&bufD4[(size_t)c * (RPB * CJ * 16) + unit],
                       &D4[((size_t)(i0 + r) * N + c * CJ) * 16 + rem]);
        }
        cp_commit();
    }

    // ---- phase 0: w[r][j] = scale * Q[i0+r] . K[j]  (L2-resident stream) ----
    for (int jb = gid * 2; jb < N; jb += 32) {
        float acc0[RPB], acc1[RPB];
        const float4 k40 = gK4[(size_t)jb * 16 + sub];
        const float4 k41 = gK4[(size_t)(jb + 1) * 16 + sub];
#pragma unroll
        for (int r = 0; r < RPB; r++) {
            acc0[r] = dot4(q_reg[r], k40);
            acc1[r] = dot4(q_reg[r], k41);
        }
        const float v0 = reduce4x16(acc0, sub);
        const float v1 = reduce4x16(acc1, sub);
        if (sub < 4) {
            w[sub * N + jb]     = v0;
            w[sub * N + jb + 1] = v1;
        }
    }

    // ---- phase 1: w[r][j] += scale * R[i0+r] . D[i0+r, j], pipelined ----
    for (int c = 0; c < NCHUNK; c++) {
        cp_wait<1>();          // chunk c landed (c+1 may still be in flight)
        __syncthreads();       // also orders phase-0 w writes before the += below

        const int b = c & 1;
        const float4* buf = bufD4 + (size_t)b * (RPB * CJ * 16);
        const int j0 = c * CJ;

#pragma unroll
        for (int dj = 0; dj < 2; dj++) {
            const int jl = gid * 2 + dj;          // 0..31 within chunk
            float acc[RPB];
#pragma unroll
            for (int r = 0; r < RPB; r++)
                acc[r] = dot4(r_reg[r], buf[(r * CJ + jl) * 16 + sub]);
            const float v = reduce4x16(acc, sub);
            if (sub < 4)
                w[sub * N + j0 + jl] += v;
        }

        __syncthreads();       // everyone done reading buf b
        if (c + 2 < NCHUNK) {
            const int cn = c + 2;
#pragma unroll
            for (int u = 0; u < 8; u++) {
                const int unit = tid + u * TPB;
                const int r = unit >> 9, rem = unit & 511;
                cp_async16(&bufD4[(size_t)b * (RPB * CJ * 16) + unit],
                           &D4[((size_t)(i0 + r) * N + cn * CJ) * 16 + rem]);
            }
        }
        cp_commit();           // unconditional: keeps group counts uniform
    }
    __syncthreads();

    // ---- phase 2: softmax, one warp per row (w already scaled) ----
    const int wid = tid >> 5;
    if (wid < RPB) {
        float m = -1e30f;
        for (int j = lane; j < N; j += 32) m = fmaxf(m, w[wid * N + j]);
#pragma unroll
        for (int o = 16; o > 0; o >>= 1) m = fmaxf(m, __shfl_xor_sync(0xFFFFFFFFu, m, o));
        float s = 0.f;
        for (int j = lane; j < N; j += 32) {
            const float p = __expf(w[wid * N + j] - m);
            w[wid * N + j] = p;
            s += p;
        }
#pragma unroll
        for (int o = 16; o > 0; o >>= 1) s += __shfl_xor_sync(0xFFFFFFFFu, s, o);
        if (lane == 0) inv_sum[wid] = 1.f / s;
    }
    __syncthreads();

    // ---- phase 3: out[i0+r] = sum_j p[r][j] * V[j] ----
    const int d = tid & 63;
    const int g = tid >> 6;
    float acc[RPB];
#pragma unroll
    for (int r = 0; r < RPB; r++) acc[r] = 0.f;

    for (int j = g; j < N; j += 4) {
        const float v = g_V[(size_t)j * DV + d];
#pragma unroll
        for (int r = 0; r < RPB; r++) acc[r] += w[r * N + j] * v;
    }

#pragma unroll
    for (int r = 0; r < RPB; r++) {
        red[tid] = acc[r];
        __syncthreads();
        if (g == 0) {
            out[(size_t)(i0 + r) * DV + d] =
                (red[d] + red[64 + d] + red[128 + d] + red[192 + d]) * inv_sum[r];
        }
        __syncthreads();
    }
}

// ---------------------------------------------------------------------------
extern "C" void kernel_launch(void* const* d_in, const int* in_sizes, int n_in,
                              void* d_out, int out_size) {
    const float* H = (const float*)d_in[0];   // (N, DIN)
    const float* D = (const float*)d_in[1];   // (N, N, DR)
    const float* W = (const float*)d_in[2];   // (PCOLS, DIN)
    float* out = (float*)d_out;               // (N, DV)

    cudaFuncSetAttribute(attn_kernel,
                         cudaFuncAttributeMaxDynamicSharedMemorySize, SMEM_BYTES);

    dim3 gb(PCOLS / 16, N / 16);
    dim3 tb(16, 16);
    proj_kernel<<<gb, tb>>>(H, W);

    attn_kernel<<<N / RPB, TPB, SMEM_BYTES>>>(D, out);
}